// round 8
// baseline (speedup 1.0000x reference)
#include <cuda_runtime.h>
#include <math.h>
#include <stdint.h>

#define N_NODES 12800
#define N_EDGES 204800
#define DIM 16
#define CHUNK 256

typedef unsigned long long ull;

// ---------------- scratch (static device memory, no allocs) ----------------
__device__ float g_out[N_NODES * DIM];
__device__ float g_hs[N_EDGES * DIM];       // edge hidden, src-sorted order
__device__ int   g_qs[N_EDGES];             // src-sorted slot -> dst-sorted slot
__device__ float g_msg0[N_EDGES * DIM];     // message ping-pong buffers
__device__ float g_msg1[N_EDGES * DIM];
__device__ int   g_src_cnt[N_NODES];        // zero at load; re-zeroed by k_scatter
__device__ int   g_dst_cnt[N_NODES];
__device__ int   g_src_off[N_NODES + 1];
__device__ int   g_dst_off[N_NODES + 1];
__device__ int   g_src_cur[N_NODES];
__device__ int   g_dst_cur[N_NODES];
__device__ float g_invdeg[N_NODES];

// ---------------- setup ----------------
// blocks [0,800): edge histograms; blocks [800,1600): lin0.
__global__ void k_hist(const float* __restrict__ x, const int* __restrict__ ei,
                       const float* __restrict__ l0w, const float* __restrict__ l0b) {
    int gb = blockIdx.x;
    if (gb < N_EDGES / 256) {
        int e = gb * 256 + threadIdx.x;
        atomicAdd(&g_src_cnt[ei[e]], 1);
        atomicAdd(&g_dst_cnt[ei[N_EDGES + e]], 1);
    } else {
        int i = (gb - N_EDGES / 256) * 256 + threadIdx.x;
        int n = i >> 4, k = i & 15;
        float acc = l0b[k];
#pragma unroll
        for (int c = 0; c < 3; ++c) acc += x[n * 3 + c] * l0w[k * 3 + c];
        g_out[i] = fmaxf(acc, 0.0f);
    }
}

// Shuffle-based exclusive scan; block 0 = src, block 1 = dst (+invdeg).
__global__ void k_scan() {
    const int PER = 13;
    int which = blockIdx.x;
    int* cnt = which ? g_dst_cnt : g_src_cnt;
    int* off = which ? g_dst_off : g_src_off;
    int* cur = which ? g_dst_cur : g_src_cur;
    int tid = threadIdx.x, lane = tid & 31, wid = tid >> 5;
    int base = tid * PER;
    int c[PER];
    int local = 0;
#pragma unroll
    for (int i = 0; i < PER; ++i) {
        int idx = base + i;
        c[i] = (idx < N_NODES) ? cnt[idx] : 0;
        local += c[i];
    }
    int incl = local;
#pragma unroll
    for (int s = 1; s < 32; s <<= 1) {
        int v = __shfl_up_sync(0xffffffffu, incl, s);
        if (lane >= s) incl += v;
    }
    __shared__ int wsum[32];
    if (lane == 31) wsum[wid] = incl;
    __syncthreads();
    if (wid == 0) {
        int v = wsum[lane];
        int iv = v;
#pragma unroll
        for (int s = 1; s < 32; s <<= 1) {
            int t = __shfl_up_sync(0xffffffffu, iv, s);
            if (lane >= s) iv += t;
        }
        wsum[lane] = iv - v;
    }
    __syncthreads();
    int run = wsum[wid] + (incl - local);
#pragma unroll
    for (int i = 0; i < PER; ++i) {
        int idx = base + i;
        if (idx < N_NODES) {
            off[idx] = run;
            cur[idx] = run;
            if (which) g_invdeg[idx] = 1.0f / fmaxf((float)c[i], 1.0f);
            run += c[i];
        }
    }
    if (tid == 1023) off[N_NODES] = run;
}

// Per edge: place into src-sorted slot, record dst slot, and compute the
// edge hidden h = relu(ea @ nn1_w^T + nn1_b) directly into g_hs[p].
// Re-zeroes count arrays for the next kernel_launch call.
__global__ void k_scatter(const int* __restrict__ ei, const float* __restrict__ ea,
                          const float* __restrict__ n1w, const float* __restrict__ n1b) {
    int e = blockIdx.x * blockDim.x + threadIdx.x;
    if (e >= N_EDGES) return;
    int s = ei[e], d = ei[N_EDGES + e];
    int p = atomicAdd(&g_src_cur[s], 1);
    int q = atomicAdd(&g_dst_cur[d], 1);
    g_qs[p] = q;
    float4 a = __ldg((const float4*)&ea[e * 4]);
    float* hd = &g_hs[p * DIM];
#pragma unroll
    for (int j = 0; j < 16; j += 4) {
        float4 h;
        h.x = fmaxf(n1b[j + 0] + a.x * n1w[(j + 0) * 4] + a.y * n1w[(j + 0) * 4 + 1] +
                    a.z * n1w[(j + 0) * 4 + 2] + a.w * n1w[(j + 0) * 4 + 3], 0.0f);
        h.y = fmaxf(n1b[j + 1] + a.x * n1w[(j + 1) * 4] + a.y * n1w[(j + 1) * 4 + 1] +
                    a.z * n1w[(j + 1) * 4 + 2] + a.w * n1w[(j + 1) * 4 + 3], 0.0f);
        h.z = fmaxf(n1b[j + 2] + a.x * n1w[(j + 2) * 4] + a.y * n1w[(j + 2) * 4 + 1] +
                    a.z * n1w[(j + 2) * 4 + 2] + a.w * n1w[(j + 2) * 4 + 3], 0.0f);
        h.w = fmaxf(n1b[j + 3] + a.x * n1w[(j + 3) * 4] + a.y * n1w[(j + 3) * 4 + 1] +
                    a.z * n1w[(j + 3) * 4 + 2] + a.w * n1w[(j + 3) * 4 + 3], 0.0f);
        *(float4*)&hd[j] = h;
    }
    if (e < N_NODES) { g_src_cnt[e] = 0; g_dst_cnt[e] = 0; }
}

// ---------------- fused per-round kernel ----------------
// 512 threads = 16 warps = 16 nodes; warp owns one node. lane = k + 16*par.
// Phase 1 (r>0): split message mean over the two half-warps, shfl-combine,
// root + ReLU + GRU (warp-private syncs only). Phase 2: P in 8 f32x2 regs
// (duplicated across halves). Phase 3: per iteration the warp processes TWO
// edges of its node from the smem-staged chunk (uniform bounds, no intra-warp
// divergence).
__global__ void __launch_bounds__(512, 2) k_round(
    const float* __restrict__ w2, const float* __restrict__ b2,
    const float* __restrict__ cr, const float* __restrict__ cb,
    const float* __restrict__ wih, const float* __restrict__ whh,
    const float* __restrict__ bih, const float* __restrict__ bhh,
    const float* __restrict__ msg_r, float* __restrict__ msg_w, int r) {
    __shared__ __align__(16) char s_raw[16384];   // w2 packed, then h chunks
    __shared__ float s_b2[256];
    __shared__ float s_cr[256];
    __shared__ float s_wih[768];                  // transposed [d][gate]
    __shared__ float s_whh[768];
    __shared__ float s_out[16][16];
    __shared__ float s_m[16][16];
    __shared__ int s_q[CHUNK];
    ull* s_w2p = (ull*)s_raw;                     // [d][jj][k]
    const ulonglong2* s_h2 = (const ulonglong2*)s_raw;
    float4* s_h4 = (float4*)s_raw;

    int tid = threadIdx.x;
    int k = tid & 15, par = (tid >> 4) & 1, g = tid >> 5;
    int n = blockIdx.x * 16 + g;

    for (int i = tid; i < 4096; i += 512) {
        int d = i >> 8, kk = (i >> 4) & 15, j = i & 15;
        ((float*)&s_w2p[(d * 8 + (j >> 1)) * 16 + kk])[j & 1] = w2[i];
    }
    if (tid < 256) { s_b2[tid] = b2[tid]; s_cr[tid] = cr[tid]; }
    for (int i = tid; i < 768; i += 512) {
        int rr = i >> 4, d = i & 15;
        s_wih[d * 48 + rr] = wih[i];
        s_whh[d * 48 + rr] = whh[i];
    }
    float hprev = g_out[n * DIM + k];
    if (par == 0) s_out[g][k] = hprev;
    __syncthreads();

    if (r > 0) {
        // ---- fused update: mean(prev msgs) + root + ReLU + GRU ----
        int beg = g_dst_off[n], end = g_dst_off[n + 1];
        float a0 = 0.0f, a1 = 0.0f;
        int q = beg + par;
        for (; q + 2 < end; q += 4) {
            a0 += __ldg(&msg_r[q * DIM + k]);
            a1 += __ldg(&msg_r[(q + 2) * DIM + k]);
        }
        if (q < end) a0 += __ldg(&msg_r[q * DIM + k]);
        float a = a0 + a1;
        a += __shfl_xor_sync(0xffffffffu, a, 16);        // combine halves
        float acc = a * g_invdeg[n] + cb[k];
#pragma unroll
        for (int d = 0; d < DIM; ++d) acc += s_out[g][d] * s_cr[d * 16 + k];
        float m = fmaxf(acc, 0.0f);
        __syncwarp();
        if (par == 0) s_m[g][k] = m;
        __syncwarp();

        float gr = bih[k], gz = bih[k + 16], gn = bih[k + 32];
        float hr = bhh[k], hz = bhh[k + 16], hn = bhh[k + 32];
#pragma unroll
        for (int d = 0; d < DIM; ++d) {
            float md = s_m[g][d], hd = s_out[g][d];
            gr += md * s_wih[d * 48 + k];
            gz += md * s_wih[d * 48 + k + 16];
            gn += md * s_wih[d * 48 + k + 32];
            hr += hd * s_whh[d * 48 + k];
            hz += hd * s_whh[d * 48 + k + 16];
            hn += hd * s_whh[d * 48 + k + 32];
        }
        float rr = 1.0f / (1.0f + expf(-(gr + hr)));
        float zz = 1.0f / (1.0f + expf(-(gz + hz)));
        float nh = tanhf(gn + rr * hn);
        float hnew = (1.0f - zz) * nh + zz * hprev;
        __syncwarp();                    // all reads of s_out complete
        if (par == 0) {
            s_out[g][k] = hnew;
            g_out[n * DIM + k] = hnew;
        }
        __syncwarp();
    }

    // ---- P-compute: P[k][j-pairs] in 8 f32x2 regs (dup across halves) ----
    ull p2[8];
    float xb = 0.0f;
#pragma unroll
    for (int jj = 0; jj < 8; ++jj) p2[jj] = 0ull;
#pragma unroll
    for (int d = 0; d < 16; ++d) {
        float od = s_out[g][d];
        ull od2;
        asm("mov.b64 %0,{%1,%1};" : "=l"(od2) : "f"(od));
        xb += od * s_b2[d * 16 + k];
#pragma unroll
        for (int jj = 0; jj < 8; ++jj) {
            ull w = s_w2p[(d * 8 + jj) * 16 + k];
            asm("fma.rn.f32x2 %0,%1,%2,%0;" : "+l"(p2[jj]) : "l"(od2), "l"(w));
        }
    }

    // ---- edge mainloop: 2 edges per warp-iteration ----
    int bn = g_src_off[n], en = g_src_off[n + 1];
    int E0 = g_src_off[blockIdx.x * 16];
    int E1 = g_src_off[blockIdx.x * 16 + 16];
    const float4* hs4 = (const float4*)g_hs;

    for (int cbase = E0; cbase < E1; cbase += CHUNK) {
        int ce = cbase + CHUNK < E1 ? cbase + CHUNK : E1;
        __syncthreads();                          // w2 reads / prior chunk done
        int cnt4 = (ce - cbase) * 4;
        for (int i4 = tid; i4 < cnt4; i4 += 512)
            s_h4[i4] = hs4[cbase * 4 + i4];       // coalesced, once per edge
        if (tid < ce - cbase) s_q[tid] = g_qs[cbase + tid];
        __syncthreads();

        int lo = bn > cbase ? bn : cbase;
        int hi = en < ce ? en : ce;
        for (int i = lo + par; i < hi; i += 2) {  // halves interleave edges
            int li = i - cbase;
            int q = s_q[li];
            ulonglong2 A = s_h2[li * 4 + 0];      // 2-addr broadcast LDS.128
            ulonglong2 B = s_h2[li * 4 + 1];
            ulonglong2 C = s_h2[li * 4 + 2];
            ulonglong2 D = s_h2[li * 4 + 3];
            ull a0, a1;
            asm("mul.rn.f32x2 %0,%1,%2;" : "=l"(a0) : "l"(A.x), "l"(p2[0]));
            asm("fma.rn.f32x2 %0,%1,%2,%0;" : "+l"(a0) : "l"(A.y), "l"(p2[1]));
            asm("fma.rn.f32x2 %0,%1,%2,%0;" : "+l"(a0) : "l"(B.x), "l"(p2[2]));
            asm("fma.rn.f32x2 %0,%1,%2,%0;" : "+l"(a0) : "l"(B.y), "l"(p2[3]));
            asm("mul.rn.f32x2 %0,%1,%2;" : "=l"(a1) : "l"(C.x), "l"(p2[4]));
            asm("fma.rn.f32x2 %0,%1,%2,%0;" : "+l"(a1) : "l"(C.y), "l"(p2[5]));
            asm("fma.rn.f32x2 %0,%1,%2,%0;" : "+l"(a1) : "l"(D.x), "l"(p2[6]));
            asm("fma.rn.f32x2 %0,%1,%2,%0;" : "+l"(a1) : "l"(D.y), "l"(p2[7]));
            asm("add.rn.f32x2 %0,%0,%1;" : "+l"(a0) : "l"(a1));
            float lo_f, hi_f;
            asm("mov.b64 {%0,%1},%2;" : "=f"(lo_f), "=f"(hi_f) : "l"(a0));
            msg_w[q * DIM + k] = lo_f + hi_f + xb;
        }
    }
}

// ---------------- final GRU-only kernel -> d_out ----------------
__global__ void k_fin(const float* __restrict__ msg_r,
                      const float* __restrict__ cr, const float* __restrict__ cb,
                      const float* __restrict__ wih, const float* __restrict__ whh,
                      const float* __restrict__ bih, const float* __restrict__ bhh,
                      float* __restrict__ outw) {
    __shared__ float s_cr[DIM * DIM];
    __shared__ float s_wih[DIM * 3 * DIM];
    __shared__ float s_whh[DIM * 3 * DIM];
    __shared__ float s_out[16][DIM];
    __shared__ float s_m[16][DIM];
    int tid = threadIdx.x;
    for (int i = tid; i < DIM * DIM; i += 256) s_cr[i] = cr[i];
    for (int i = tid; i < 3 * DIM * DIM; i += 256) {
        int r = i >> 4, d = i & 15;
        s_wih[d * 48 + r] = wih[i];
        s_whh[d * 48 + r] = whh[i];
    }
    int ln = tid >> 4, k = tid & 15;
    int n = blockIdx.x * 16 + ln;
    float hprev = g_out[n * DIM + k];
    s_out[ln][k] = hprev;
    __syncthreads();

    int beg = g_dst_off[n], end = g_dst_off[n + 1];
    float a0 = 0.0f, a1 = 0.0f, a2 = 0.0f, a3 = 0.0f;
    int q = beg;
    for (; q + 3 < end; q += 4) {
        a0 += __ldg(&msg_r[(q + 0) * DIM + k]);
        a1 += __ldg(&msg_r[(q + 1) * DIM + k]);
        a2 += __ldg(&msg_r[(q + 2) * DIM + k]);
        a3 += __ldg(&msg_r[(q + 3) * DIM + k]);
    }
    for (; q < end; ++q) a0 += __ldg(&msg_r[q * DIM + k]);
    float acc = ((a0 + a1) + (a2 + a3)) * g_invdeg[n] + cb[k];
#pragma unroll
    for (int d = 0; d < DIM; ++d) acc += s_out[ln][d] * s_cr[d * DIM + k];
    float m = fmaxf(acc, 0.0f);
    s_m[ln][k] = m;
    __syncthreads();

    float gr = bih[k], gz = bih[k + 16], gn = bih[k + 32];
    float hr = bhh[k], hz = bhh[k + 16], hn = bhh[k + 32];
#pragma unroll
    for (int d = 0; d < DIM; ++d) {
        float md = s_m[ln][d], hd = s_out[ln][d];
        gr += md * s_wih[d * 48 + k];
        gz += md * s_wih[d * 48 + k + 16];
        gn += md * s_wih[d * 48 + k + 32];
        hr += hd * s_whh[d * 48 + k];
        hz += hd * s_whh[d * 48 + k + 16];
        hn += hd * s_whh[d * 48 + k + 32];
    }
    float r = 1.0f / (1.0f + expf(-(gr + hr)));
    float z = 1.0f / (1.0f + expf(-(gz + hz)));
    float nh = tanhf(gn + r * hn);
    outw[n * DIM + k] = (1.0f - z) * nh + z * hprev;
}

// ---------------- host launcher ----------------
extern "C" void kernel_launch(void* const* d_in, const int* in_sizes, int n_in,
                              void* d_out, int out_size) {
    const float* x         = (const float*)d_in[0];
    const int*   ei        = (const int*)  d_in[1];
    const float* ea        = (const float*)d_in[2];
    const float* lin0_w    = (const float*)d_in[3];
    const float* lin0_b    = (const float*)d_in[4];
    const float* nn1_w     = (const float*)d_in[5];
    const float* nn1_b     = (const float*)d_in[6];
    const float* nn2_w     = (const float*)d_in[7];
    const float* nn2_b     = (const float*)d_in[8];
    const float* conv_root = (const float*)d_in[9];
    const float* conv_bias = (const float*)d_in[10];
    const float* w_ih      = (const float*)d_in[11];
    const float* w_hh      = (const float*)d_in[12];
    const float* b_ih      = (const float*)d_in[13];
    const float* b_hh      = (const float*)d_in[14];

    float *m0 = nullptr, *m1 = nullptr;
    cudaGetSymbolAddress((void**)&m0, g_msg0);
    cudaGetSymbolAddress((void**)&m1, g_msg1);

    k_hist<<<N_EDGES / 256 + (N_NODES * DIM) / 256, 256>>>(x, ei, lin0_w, lin0_b);
    k_scan<<<2, 1024>>>();
    k_scatter<<<(N_EDGES + 255) / 256, 256>>>(ei, ea, nn1_w, nn1_b);

    for (int r = 0; r < 6; ++r) {
        const float* mr = ((r - 1) & 1) ? m1 : m0;   // buffer written by round r-1
        float* mw = (r & 1) ? m1 : m0;
        k_round<<<N_NODES / 16, 512>>>(nn2_w, nn2_b, conv_root, conv_bias,
                                       w_ih, w_hh, b_ih, b_hh, mr, mw, r);
    }
    k_fin<<<N_NODES / 16, 256>>>(m1, conv_root, conv_bias, w_ih, w_hh,
                                 b_ih, b_hh, (float*)d_out);
}

// round 9
// speedup vs baseline: 1.1467x; 1.1467x over previous
#include <cuda_runtime.h>
#include <math.h>
#include <stdint.h>

#define N_NODES 12800
#define N_EDGES 204800
#define DIM 16
#define CHUNK 256

typedef unsigned long long ull;

// ---------------- scratch (static device memory, no allocs) ----------------
__device__ float g_out[N_NODES * DIM];
__device__ float g_hs[N_EDGES * DIM];       // edge hidden, src-sorted order
__device__ int   g_dst[N_EDGES];            // dst node id per src-sorted slot
__device__ float g_aggr0[N_NODES * DIM];    // aggregation ping-pong (RED targets)
__device__ float g_aggr1[N_NODES * DIM];    // zero at load; each reader re-zeroes
__device__ int   g_src_cnt[N_NODES];        // zero at load; re-zeroed by k_scatter
__device__ int   g_dst_cnt[N_NODES];        // zero at load; re-zeroed by k_scan
__device__ int   g_src_off[N_NODES + 1];
__device__ int   g_src_cur[N_NODES];
__device__ float g_invdeg[N_NODES];

// ---------------- setup ----------------
// blocks [0,800): edge histograms; blocks [800,1600): lin0.
__global__ void k_hist(const float* __restrict__ x, const int* __restrict__ ei,
                       const float* __restrict__ l0w, const float* __restrict__ l0b) {
    int gb = blockIdx.x;
    if (gb < N_EDGES / 256) {
        int e = gb * 256 + threadIdx.x;
        atomicAdd(&g_src_cnt[ei[e]], 1);
        atomicAdd(&g_dst_cnt[ei[N_EDGES + e]], 1);
    } else {
        int i = (gb - N_EDGES / 256) * 256 + threadIdx.x;
        int n = i >> 4, k = i & 15;
        float acc = l0b[k];
#pragma unroll
        for (int c = 0; c < 3; ++c) acc += x[n * 3 + c] * l0w[k * 3 + c];
        g_out[i] = fmaxf(acc, 0.0f);
    }
}

// block 0: shuffle-based exclusive scan of src counts (+cursor init).
// block 1: invdeg from dst counts, then re-zero dst counts for next call.
__global__ void k_scan() {
    if (blockIdx.x == 1) {
        for (int i = threadIdx.x; i < N_NODES; i += 1024) {
            g_invdeg[i] = 1.0f / fmaxf((float)g_dst_cnt[i], 1.0f);
            g_dst_cnt[i] = 0;
        }
        return;
    }
    const int PER = 13;
    int tid = threadIdx.x, lane = tid & 31, wid = tid >> 5;
    int base = tid * PER;
    int c[PER];
    int local = 0;
#pragma unroll
    for (int i = 0; i < PER; ++i) {
        int idx = base + i;
        c[i] = (idx < N_NODES) ? g_src_cnt[idx] : 0;
        local += c[i];
    }
    int incl = local;
#pragma unroll
    for (int s = 1; s < 32; s <<= 1) {
        int v = __shfl_up_sync(0xffffffffu, incl, s);
        if (lane >= s) incl += v;
    }
    __shared__ int wsum[32];
    if (lane == 31) wsum[wid] = incl;
    __syncthreads();
    if (wid == 0) {
        int v = wsum[lane];
        int iv = v;
#pragma unroll
        for (int s = 1; s < 32; s <<= 1) {
            int t = __shfl_up_sync(0xffffffffu, iv, s);
            if (lane >= s) iv += t;
        }
        wsum[lane] = iv - v;
    }
    __syncthreads();
    int run = wsum[wid] + (incl - local);
#pragma unroll
    for (int i = 0; i < PER; ++i) {
        int idx = base + i;
        if (idx < N_NODES) {
            g_src_off[idx] = run;
            g_src_cur[idx] = run;
            run += c[i];
        }
    }
    if (tid == 1023) g_src_off[N_NODES] = run;
}

// Per edge: place into src-sorted slot p, record dst node id, compute edge
// hidden h = relu(ea @ nn1_w^T + nn1_b) directly into g_hs[p].
// Re-zeroes src counts for the next kernel_launch call.
__global__ void k_scatter(const int* __restrict__ ei, const float* __restrict__ ea,
                          const float* __restrict__ n1w, const float* __restrict__ n1b) {
    int e = blockIdx.x * blockDim.x + threadIdx.x;
    if (e >= N_EDGES) return;
    int s = ei[e], d = ei[N_EDGES + e];
    int p = atomicAdd(&g_src_cur[s], 1);
    g_dst[p] = d;
    float4 a = __ldg((const float4*)&ea[e * 4]);
    float* hd = &g_hs[p * DIM];
#pragma unroll
    for (int j = 0; j < 16; j += 4) {
        float4 h;
        h.x = fmaxf(n1b[j + 0] + a.x * n1w[(j + 0) * 4] + a.y * n1w[(j + 0) * 4 + 1] +
                    a.z * n1w[(j + 0) * 4 + 2] + a.w * n1w[(j + 0) * 4 + 3], 0.0f);
        h.y = fmaxf(n1b[j + 1] + a.x * n1w[(j + 1) * 4] + a.y * n1w[(j + 1) * 4 + 1] +
                    a.z * n1w[(j + 1) * 4 + 2] + a.w * n1w[(j + 1) * 4 + 3], 0.0f);
        h.z = fmaxf(n1b[j + 2] + a.x * n1w[(j + 2) * 4] + a.y * n1w[(j + 2) * 4 + 1] +
                    a.z * n1w[(j + 2) * 4 + 2] + a.w * n1w[(j + 2) * 4 + 3], 0.0f);
        h.w = fmaxf(n1b[j + 3] + a.x * n1w[(j + 3) * 4] + a.y * n1w[(j + 3) * 4 + 1] +
                    a.z * n1w[(j + 3) * 4 + 2] + a.w * n1w[(j + 3) * 4 + 3], 0.0f);
        *(float4*)&hd[j] = h;
    }
    if (e < N_NODES) g_src_cnt[e] = 0;
}

// ---------------- fused per-round kernel ----------------
// 512 threads = 16 warps = 16 nodes; WARP owns one node (uniform loop bounds).
// lane = k + 16*par. Phase 1 (r>0): read aggr (then zero it for reuse), root
// matmul + ReLU + GRU. Phase 2: each half keeps its 4 P j-pairs in f32x2 regs.
// Phase 3: whole warp processes ONE edge per iteration; par halves split the
// h vector (each 2x LDS.128 @ 2 unique addrs = 1 wavefront), shfl_xor(16)
// combines partial dots, par0 REDs the message into aggr_w[dst].
__global__ void __launch_bounds__(512) k_round(
    const float* __restrict__ w2, const float* __restrict__ b2,
    const float* __restrict__ cr, const float* __restrict__ cb,
    const float* __restrict__ wih, const float* __restrict__ whh,
    const float* __restrict__ bih, const float* __restrict__ bhh,
    float* __restrict__ aggr_r, float* __restrict__ aggr_w, int r) {
    __shared__ __align__(16) char s_raw[16384];   // w2 packed, then h chunks
    __shared__ int s_dst[CHUNK];
    __shared__ float s_b2[256];
    __shared__ float s_cr[256];
    __shared__ float s_wih[768];                  // transposed [d][gate]
    __shared__ float s_whh[768];
    __shared__ float s_out[16][16];
    __shared__ float s_m[16][16];
    ull* s_w2p = (ull*)s_raw;                     // [d][jj][k]
    const ulonglong2* s_h2 = (const ulonglong2*)s_raw;
    float4* s_h4 = (float4*)s_raw;

    int tid = threadIdx.x;
    int lane = tid & 31, k = lane & 15, par = lane >> 4, w = tid >> 5;
    int n = blockIdx.x * 16 + w;

    for (int i = tid; i < 4096; i += 512) {
        int d = i >> 8, kk = (i >> 4) & 15, j = i & 15;
        ((float*)&s_w2p[(d * 8 + (j >> 1)) * 16 + kk])[j & 1] = w2[i];
    }
    if (tid < 256) { s_b2[tid] = b2[tid]; s_cr[tid] = cr[tid]; }
    for (int i = tid; i < 768; i += 512) {
        int rr = i >> 4, d = i & 15;
        s_wih[d * 48 + rr] = wih[i];
        s_whh[d * 48 + rr] = whh[i];
    }
    float hprev = g_out[n * DIM + k];             // halves duplicate (broadcast)
    if (par == 0) s_out[w][k] = hprev;
    __syncthreads();

    if (r > 0) {
        // ---- fused update: aggr read (+ re-zero) + root + ReLU + GRU ----
        float v = aggr_r[n * DIM + k];
        if (par == 0) aggr_r[n * DIM + k] = 0.0f; // zero for round r+1's REDs
        float acc = v * g_invdeg[n] + cb[k];
#pragma unroll
        for (int d = 0; d < DIM; ++d) acc += s_out[w][d] * s_cr[d * 16 + k];
        float m = fmaxf(acc, 0.0f);
        __syncwarp();
        if (par == 0) s_m[w][k] = m;
        __syncwarp();

        float gr = bih[k], gz = bih[k + 16], gn = bih[k + 32];
        float hr = bhh[k], hz = bhh[k + 16], hn = bhh[k + 32];
#pragma unroll
        for (int d = 0; d < DIM; ++d) {
            float md = s_m[w][d], hd = s_out[w][d];
            gr += md * s_wih[d * 48 + k];
            gz += md * s_wih[d * 48 + k + 16];
            gn += md * s_wih[d * 48 + k + 32];
            hr += hd * s_whh[d * 48 + k];
            hz += hd * s_whh[d * 48 + k + 16];
            hn += hd * s_whh[d * 48 + k + 32];
        }
        float rr = 1.0f / (1.0f + expf(-(gr + hr)));
        float zz = 1.0f / (1.0f + expf(-(gz + hz)));
        float nh = tanhf(gn + rr * hn);
        float hnew = (1.0f - zz) * nh + zz * hprev;
        __syncwarp();                    // all reads of s_out complete
        if (par == 0) {
            s_out[w][k] = hnew;
            g_out[n * DIM + k] = hnew;
        }
        __syncwarp();
    }

    // ---- P-compute: this half's 4 j-pairs of P[k][:] in f32x2 regs ----
    ull p2[4];
    float xb = 0.0f;
#pragma unroll
    for (int jj = 0; jj < 4; ++jj) p2[jj] = 0ull;
#pragma unroll
    for (int d = 0; d < 16; ++d) {
        float od = s_out[w][d];
        ull od2;
        asm("mov.b64 %0,{%1,%1};" : "=l"(od2) : "f"(od));
        xb += od * s_b2[d * 16 + k];
#pragma unroll
        for (int jj = 0; jj < 4; ++jj) {
            ull wv = s_w2p[(d * 8 + par * 4 + jj) * 16 + k];
            asm("fma.rn.f32x2 %0,%1,%2,%0;" : "+l"(p2[jj]) : "l"(od2), "l"(wv));
        }
    }

    // ---- edge mainloop: one edge per warp-iteration, halves split h ----
    int bn = g_src_off[n], en = g_src_off[n + 1];
    int E0 = g_src_off[blockIdx.x * 16];
    int E1 = g_src_off[blockIdx.x * 16 + 16];
    const float4* hs4 = (const float4*)g_hs;

    for (int cbase = E0; cbase < E1; cbase += CHUNK) {
        int ce = cbase + CHUNK < E1 ? cbase + CHUNK : E1;
        __syncthreads();                          // w2 reads / prior chunk done
        int cnt4 = (ce - cbase) * 4;
        for (int i4 = tid; i4 < cnt4; i4 += 512)
            s_h4[i4] = hs4[cbase * 4 + i4];       // coalesced, once per edge
        if (tid < ce - cbase) s_dst[tid] = g_dst[cbase + tid];
        __syncthreads();

        int lo = bn > cbase ? bn : cbase;
        int hi = en < ce ? en : ce;
        for (int i = lo; i < hi; ++i) {
            int li = i - cbase;
            int dst = s_dst[li];                  // warp-uniform broadcast
            ulonglong2 X = s_h2[li * 4 + par * 2];     // 2 addrs/warp = 1 wf
            ulonglong2 Y = s_h2[li * 4 + par * 2 + 1];
            ull a;
            asm("mul.rn.f32x2 %0,%1,%2;" : "=l"(a) : "l"(X.x), "l"(p2[0]));
            asm("fma.rn.f32x2 %0,%1,%2,%0;" : "+l"(a) : "l"(X.y), "l"(p2[1]));
            asm("fma.rn.f32x2 %0,%1,%2,%0;" : "+l"(a) : "l"(Y.x), "l"(p2[2]));
            asm("fma.rn.f32x2 %0,%1,%2,%0;" : "+l"(a) : "l"(Y.y), "l"(p2[3]));
            float lo_f, hi_f;
            asm("mov.b64 {%0,%1},%2;" : "=f"(lo_f), "=f"(hi_f) : "l"(a));
            float t = lo_f + hi_f;
            t += __shfl_xor_sync(0xffffffffu, t, 16);   // combine halves
            if (par == 0)
                atomicAdd(&aggr_w[dst * DIM + k], t + xb);   // REDG, no return
        }
    }
}

// ---------------- final GRU-only kernel -> d_out ----------------
__global__ void k_fin(float* __restrict__ aggr_r,
                      const float* __restrict__ cr, const float* __restrict__ cb,
                      const float* __restrict__ wih, const float* __restrict__ whh,
                      const float* __restrict__ bih, const float* __restrict__ bhh,
                      float* __restrict__ outw) {
    __shared__ float s_cr[DIM * DIM];
    __shared__ float s_wih[DIM * 3 * DIM];
    __shared__ float s_whh[DIM * 3 * DIM];
    __shared__ float s_out[16][DIM];
    __shared__ float s_m[16][DIM];
    int tid = threadIdx.x;
    for (int i = tid; i < DIM * DIM; i += 256) s_cr[i] = cr[i];
    for (int i = tid; i < 3 * DIM * DIM; i += 256) {
        int r = i >> 4, d = i & 15;
        s_wih[d * 48 + r] = wih[i];
        s_whh[d * 48 + r] = whh[i];
    }
    int ln = tid >> 4, k = tid & 15;
    int n = blockIdx.x * 16 + ln;
    float hprev = g_out[n * DIM + k];
    s_out[ln][k] = hprev;
    __syncthreads();

    float v = aggr_r[n * DIM + k];
    aggr_r[n * DIM + k] = 0.0f;                   // restore for next call
    float acc = v * g_invdeg[n] + cb[k];
#pragma unroll
    for (int d = 0; d < DIM; ++d) acc += s_out[ln][d] * s_cr[d * DIM + k];
    float m = fmaxf(acc, 0.0f);
    s_m[ln][k] = m;
    __syncthreads();

    float gr = bih[k], gz = bih[k + 16], gn = bih[k + 32];
    float hr = bhh[k], hz = bhh[k + 16], hn = bhh[k + 32];
#pragma unroll
    for (int d = 0; d < DIM; ++d) {
        float md = s_m[ln][d], hd = s_out[ln][d];
        gr += md * s_wih[d * 48 + k];
        gz += md * s_wih[d * 48 + k + 16];
        gn += md * s_wih[d * 48 + k + 32];
        hr += hd * s_whh[d * 48 + k];
        hz += hd * s_whh[d * 48 + k + 16];
        hn += hd * s_whh[d * 48 + k + 32];
    }
    float r = 1.0f / (1.0f + expf(-(gr + hr)));
    float z = 1.0f / (1.0f + expf(-(gz + hz)));
    float nh = tanhf(gn + r * hn);
    outw[n * DIM + k] = (1.0f - z) * nh + z * hprev;
}

// ---------------- host launcher ----------------
extern "C" void kernel_launch(void* const* d_in, const int* in_sizes, int n_in,
                              void* d_out, int out_size) {
    const float* x         = (const float*)d_in[0];
    const int*   ei        = (const int*)  d_in[1];
    const float* ea        = (const float*)d_in[2];
    const float* lin0_w    = (const float*)d_in[3];
    const float* lin0_b    = (const float*)d_in[4];
    const float* nn1_w     = (const float*)d_in[5];
    const float* nn1_b     = (const float*)d_in[6];
    const float* nn2_w     = (const float*)d_in[7];
    const float* nn2_b     = (const float*)d_in[8];
    const float* conv_root = (const float*)d_in[9];
    const float* conv_bias = (const float*)d_in[10];
    const float* w_ih      = (const float*)d_in[11];
    const float* w_hh      = (const float*)d_in[12];
    const float* b_ih      = (const float*)d_in[13];
    const float* b_hh      = (const float*)d_in[14];

    float *a0 = nullptr, *a1 = nullptr;
    cudaGetSymbolAddress((void**)&a0, g_aggr0);
    cudaGetSymbolAddress((void**)&a1, g_aggr1);

    k_hist<<<N_EDGES / 256 + (N_NODES * DIM) / 256, 256>>>(x, ei, lin0_w, lin0_b);
    k_scan<<<2, 1024>>>();
    k_scatter<<<(N_EDGES + 255) / 256, 256>>>(ei, ea, nn1_w, nn1_b);

    // round r REDs into A[r&1]; round r+1 reads A[r&1] and zeroes it after
    // reading (its REDs go to the other buffer). Both buffers are zero at
    // call entry (zero-initialized at load; every reader restores zeros).
    for (int r = 0; r < 6; ++r) {
        float* ar = ((r - 1) & 1) ? a1 : a0;   // buffer round r-1 REDed into
        float* aw = (r & 1) ? a1 : a0;
        k_round<<<N_NODES / 16, 512>>>(nn2_w, nn2_b, conv_root, conv_bias,
                                       w_ih, w_hh, b_ih, b_hh, ar, aw, r);
    }
    k_fin<<<N_NODES / 16, 256>>>(a1, conv_root, conv_bias, w_ih, w_hh,
                                 b_ih, b_hh, (float*)d_out);
}